// round 13
// baseline (speedup 1.0000x reference)
#include <cuda_runtime.h>
#include <cuda_pipeline_primitives.h>

// Problem constants (fixed by the reference):
//   image 1000x1000, patch 5x5 -> 200x200 = 40000 patches
//   coefficients [40000, 3, 10, 2], bias [40000, 3]
//   out [3, 1000000]
#define IMG_W           1000
#define NUM_PIX         1000000
#define PATCH           5
#define PATCHES_PER_ROW 200
#define COEF_PER_PATCH  60          // 3*10*2
#define NTHREADS        256         // 8 warps x 5 patches = 40 patches/block
#define GRID            1000
#define WARP_F          300         // 5 patches * 60 floats of smem per warp

// Packed dual-FP32 FMA (Blackwell)
__device__ __forceinline__ unsigned long long ffma2(unsigned long long a,
                                                    unsigned long long b,
                                                    unsigned long long c)
{
    unsigned long long d;
    asm("fma.rn.f32x2 %0, %1, %2, %3;" : "=l"(d) : "l"(a), "l"(b), "l"(c));
    return d;
}
__device__ __forceinline__ unsigned long long as_u64(double v)
{
    return __double_as_longlong(v);
}
__device__ __forceinline__ float hsum2(unsigned long long v)
{
    float lo, hi;
    asm("mov.b64 {%0, %1}, %2;" : "=f"(lo), "=f"(hi) : "l"(v));
    return lo + hi;
}
__device__ __forceinline__ unsigned long long pack2(float lo, float hi)
{
    unsigned long long r;
    asm("mov.b64 %0, {%1, %2};" : "=l"(r) : "f"(lo), "f"(hi));
    return r;
}

// Warp-autonomous with smem coefficient staging. NO __syncthreads:
// each warp cp.asyncs its own 5 patches (1200B contiguous), waits on its own
// group, __syncwarp, computes. Warps drain staggered -- no block convoy.
__global__ __launch_bounds__(NTHREADS, 6)
void ts_kernel(const float* __restrict__ pix,
               const float* __restrict__ coef,
               const float* __restrict__ bias,
               float* __restrict__ out)
{
    __shared__ __align__(16) float sc[8 * WARP_F];   // 9600 B

    const int tid  = threadIdx.x;
    const int w    = tid >> 5;
    const int lane = tid & 31;

    const int b   = blockIdx.x;          // 0..999
    const int pr  = b / 5;               // patch row 0..199
    const int cb  = (b - pr * 5) * 40;   // patch-col base of block
    const int pw  = pr * PATCHES_PER_ROW + cb + w * 5;   // warp's first patch

    // ---- Warp-local coefficient staging: 75 float4, contiguous ----
    {
        const float4* g4 = (const float4*)(coef + (size_t)pw * COEF_PER_PATCH);
        float* dst = &sc[w * WARP_F];
        #pragma unroll
        for (int k = 0; k < 3; k++) {
            int idx = lane + k * 32;
            if (idx < 75)
                __pipeline_memcpy_async(&dst[idx * 4], &g4[idx], 16);
        }
        __pipeline_commit();
    }

    const int q = lane / 5;              // patch within warp (0..4)
    const int s = lane % 5;              // pixel row within patch (0..4)
    const bool active = (lane < 25);

    const int pg      = pw + q;          // global patch id
    const int pixBase = (pr * PATCH + s) * IMG_W + (cb + w * 5 + q) * PATCH;

    // ---- Early independent loads: pixels + bias overlap the cp.async drain ----
    unsigned long long xy[PATCH];
    float bv[3];
    if (active) {
        const double* pp8 = (const double*)pix + pixBase;
        #pragma unroll
        for (int i = 0; i < PATCH; i++)
            xy[i] = as_u64(pp8[i]);
        const float* bp = bias + (size_t)pg * 3;
        #pragma unroll
        for (int ch = 0; ch < 3; ch++)
            bv[ch] = __ldg(bp + ch);     // 5-lane broadcast groups
    }

    __pipeline_wait_prior(0);
    __syncwarp();                        // own-warp smem visibility only

    if (!active) return;

    const float* cc0 = &sc[w * WARP_F + q * COEF_PER_PATCH];  // bcast, conflict-free
    float* o = out + pixBase;

    #pragma unroll
    for (int ch = 0; ch < 3; ch++) {
        const double2* cp = (const double2*)(cc0 + ch * 20);  // 16B-aligned

        double2 p4 = cp[4];  // (cx8,cy8 | cx9,cy9)
        double2 p3 = cp[3];
        double2 p2 = cp[2];
        double2 p1 = cp[1];
        double2 p0 = cp[0];  // (cx0,cy0 | cx1,cy1)

        // Fold bias into cx0: final hsum gives rx+ry+bias with no epilogue add.
        unsigned long long c0;
        {
            float lo, hi;
            asm("mov.b64 {%0, %1}, %2;" : "=f"(lo), "=f"(hi) : "l"(as_u64(p0.x)));
            c0 = pack2(lo + bv[ch], hi);
        }

        unsigned long long acc[PATCH];
        {
            const unsigned long long c8 = as_u64(p4.x), c9 = as_u64(p4.y);
            #pragma unroll
            for (int i = 0; i < PATCH; i++)
                acc[i] = ffma2(c9, xy[i], c8);       // t=9 -> t=8
        }
        {
            const unsigned long long clo = as_u64(p3.x), chi = as_u64(p3.y);
            #pragma unroll
            for (int i = 0; i < PATCH; i++) acc[i] = ffma2(acc[i], xy[i], chi);
            #pragma unroll
            for (int i = 0; i < PATCH; i++) acc[i] = ffma2(acc[i], xy[i], clo);
        }
        {
            const unsigned long long clo = as_u64(p2.x), chi = as_u64(p2.y);
            #pragma unroll
            for (int i = 0; i < PATCH; i++) acc[i] = ffma2(acc[i], xy[i], chi);
            #pragma unroll
            for (int i = 0; i < PATCH; i++) acc[i] = ffma2(acc[i], xy[i], clo);
        }
        {
            const unsigned long long clo = as_u64(p1.x), chi = as_u64(p1.y);
            #pragma unroll
            for (int i = 0; i < PATCH; i++) acc[i] = ffma2(acc[i], xy[i], chi);
            #pragma unroll
            for (int i = 0; i < PATCH; i++) acc[i] = ffma2(acc[i], xy[i], clo);
        }
        {
            const unsigned long long chi = as_u64(p0.y);
            #pragma unroll
            for (int i = 0; i < PATCH; i++) acc[i] = ffma2(acc[i], xy[i], chi);
            #pragma unroll
            for (int i = 0; i < PATCH; i++) acc[i] = ffma2(acc[i], xy[i], c0);
        }

        float* oc = o + ch * NUM_PIX;
        #pragma unroll
        for (int i = 0; i < PATCH; i++)
            oc[i] = hsum2(acc[i]);                   // rx + ry + bias
    }
}

extern "C" void kernel_launch(void* const* d_in, const int* in_sizes, int n_in,
                              void* d_out, int out_size)
{
    const float* pix  = (const float*)d_in[0];   // [1000000, 2]
    const float* coef = (const float*)d_in[1];   // [40000, 3, 10, 2]
    const float* bias = (const float*)d_in[2];   // [40000, 3]
    float* out = (float*)d_out;                  // [3, 1000000]

    (void)in_sizes; (void)n_in; (void)out_size;
    ts_kernel<<<GRID, NTHREADS>>>(pix, coef, bias, out);
}

// round 14
// speedup vs baseline: 1.1192x; 1.1192x over previous
#include <cuda_runtime.h>
#include <cuda_pipeline_primitives.h>

// Problem constants (fixed by the reference):
//   image 1000x1000, patch 5x5 -> 200x200 = 40000 patches
//   coefficients [40000, 3, 10, 2], bias [40000, 3]
//   out [3, 1000000]
#define IMG_W           1000
#define NUM_PIX         1000000
#define PATCH           5
#define NUM_PATCHES     40000
#define COEF_PER_PATCH  60          // 3*10*2
#define PB              46          // consecutive patches per block (row-major, may wrap)
#define NTHREADS        256         // 230 compute threads (89.8% active)
#define GRID            870         // 869 full tiles + 1 tail (26 patches); single wave @6/SM

// Packed dual-FP32 FMA (Blackwell)
__device__ __forceinline__ unsigned long long ffma2(unsigned long long a,
                                                    unsigned long long b,
                                                    unsigned long long c)
{
    unsigned long long d;
    asm("fma.rn.f32x2 %0, %1, %2, %3;" : "=l"(d) : "l"(a), "l"(b), "l"(c));
    return d;
}
__device__ __forceinline__ unsigned long long as_u64(double v)
{
    return __double_as_longlong(v);
}
__device__ __forceinline__ float hsum2(unsigned long long v)
{
    float lo, hi;
    asm("mov.b64 {%0, %1}, %2;" : "=f"(lo), "=f"(hi) : "l"(v));
    return lo + hi;
}

__global__ __launch_bounds__(NTHREADS, 6)
void ts_kernel(const float* __restrict__ pix,
               const float* __restrict__ coef,
               const float* __restrict__ bias,
               float* __restrict__ out)
{
    __shared__ float sc[PB * COEF_PER_PATCH];   // 2760 floats, LINEAR (11040 B)
    __shared__ float sb[PB * 3 + 2];            // bias (138 used)

    const int tid    = threadIdx.x;
    const int b      = blockIdx.x;                    // 0..869
    const int pstart = b * PB;                        // first global patch of tile
    const int np     = min(PB, NUM_PATCHES - pstart); // 46, or 26 for tail block

    // ---- Coefficient + bias staging (cp.async; coeffs 16B, bias 8B granules) ----
    {
        // np*15 float4, contiguous (pstart*240B is 16B-aligned).
        const float4* g4 = (const float4*)(coef + (size_t)pstart * COEF_PER_PATCH);
        const int nf4 = np * 15;
        #pragma unroll
        for (int k = 0; k < 3; k++) {
            int idx = tid + k * NTHREADS;
            if (idx < nf4)
                __pipeline_memcpy_async(&sc[idx * 4], &g4[idx], 16);
        }
        // Bias: np*3 floats; byte offset b*552 is 8B-aligned, count even -> float2.
        if (tid < (np * 3) / 2)
            __pipeline_memcpy_async(&sb[tid * 2],
                                    (const float2*)(bias + (size_t)pstart * 3) + tid, 8);
        __pipeline_commit();
    }

    // ---- Early pixel loads (independent of smem; overlap the coeff wait) ----
    const int p_local = tid % PB;        // 0..45 (consecutive patches within warp)
    const int seg     = tid / PB;        // 0..5 (only 0..4 compute)
    const bool active = (p_local < np) && (seg < PATCH);

    // Global patch -> pixel base (tile may wrap patch rows; per-thread decode)
    const int pg   = pstart + p_local;
    const int prow = pg / 200;           // patch row 0..199 (IMAD.HI magic)
    const int pcol = pg - prow * 200;    // patch col 0..199
    const int pixBase = (prow * PATCH + seg) * IMG_W + pcol * PATCH;

    unsigned long long xy[PATCH];
    if (active) {
        const double* pp8 = (const double*)pix + pixBase;   // pixel n = double n
        #pragma unroll
        for (int i = 0; i < PATCH; i++)
            xy[i] = as_u64(pp8[i]);
    }

    __pipeline_wait_prior(0);
    __syncthreads();

    // ---- Compute + direct stores (thread = 5-pixel segment of one patch) ----
    if (active) {
        const float* cc0 = &sc[p_local * COEF_PER_PATCH];   // 240B stride: conflict-free LDS.128
        const float bv0 = sb[p_local * 3 + 0];
        const float bv1 = sb[p_local * 3 + 1];
        const float bv2 = sb[p_local * 3 + 2];
        float* o = out + pixBase;

        #pragma unroll
        for (int ch = 0; ch < 3; ch++) {
            const double2* cp = (const double2*)(cc0 + ch * 20);  // 16B-aligned
            const float bv = (ch == 0) ? bv0 : (ch == 1) ? bv1 : bv2;

            unsigned long long acc[PATCH];
            {
                double2 v = cp[4];                       // pairs t=8, t=9
                const unsigned long long c8 = as_u64(v.x), c9 = as_u64(v.y);
                #pragma unroll
                for (int i = 0; i < PATCH; i++)
                    acc[i] = ffma2(c9, xy[i], c8);
            }
            #pragma unroll
            for (int j = 3; j >= 0; j--) {
                double2 v = cp[j];                       // pairs t=2j, t=2j+1
                const unsigned long long clo = as_u64(v.x), chi = as_u64(v.y);
                #pragma unroll
                for (int i = 0; i < PATCH; i++)
                    acc[i] = ffma2(acc[i], xy[i], chi);
                #pragma unroll
                for (int i = 0; i < PATCH; i++)
                    acc[i] = ffma2(acc[i], xy[i], clo);
            }
            float* oc = o + ch * NUM_PIX;
            #pragma unroll
            for (int i = 0; i < PATCH; i++)
                oc[i] = hsum2(acc[i]) + bv;              // warp run: contiguous stores
        }
    }
}

extern "C" void kernel_launch(void* const* d_in, const int* in_sizes, int n_in,
                              void* d_out, int out_size)
{
    const float* pix  = (const float*)d_in[0];   // [1000000, 2]
    const float* coef = (const float*)d_in[1];   // [40000, 3, 10, 2]
    const float* bias = (const float*)d_in[2];   // [40000, 3]
    float* out = (float*)d_out;                  // [3, 1000000]

    (void)in_sizes; (void)n_in; (void)out_size;
    ts_kernel<<<GRID, NTHREADS>>>(pix, coef, bias, out);
}

// round 15
// speedup vs baseline: 1.3368x; 1.1944x over previous
#include <cuda_runtime.h>
#include <cuda_pipeline_primitives.h>

// Problem constants (fixed by the reference):
//   image 1000x1000, patch 5x5 -> 200x200 = 40000 patches
//   coefficients [40000, 3, 10, 2], bias [40000, 3]
//   out [3, 1000000]
#define IMG_W           1000
#define NUM_PIX         1000000
#define PATCH           5
#define PATCHES_PER_ROW 200
#define COEF_PER_PATCH  60          // 3*10*2
#define PB              40          // patches per block (one fifth of a patch-row)
#define NTHREADS        224         // 7 warps; 200 compute threads (89.3% active)
#define GRID            1000        // < 148*7 = 1036 -> exactly one wave

// Packed dual-FP32 FMA (Blackwell)
__device__ __forceinline__ unsigned long long ffma2(unsigned long long a,
                                                    unsigned long long b,
                                                    unsigned long long c)
{
    unsigned long long d;
    asm("fma.rn.f32x2 %0, %1, %2, %3;" : "=l"(d) : "l"(a), "l"(b), "l"(c));
    return d;
}
__device__ __forceinline__ unsigned long long as_u64(double v)
{
    return __double_as_longlong(v);
}
__device__ __forceinline__ float hsum2(unsigned long long v)
{
    float lo, hi;
    asm("mov.b64 {%0, %1}, %2;" : "=f"(lo), "=f"(hi) : "l"(v));
    return lo + hi;
}

__global__ __launch_bounds__(NTHREADS, 7)
void ts_kernel(const float* __restrict__ pix,
               const float* __restrict__ coef,
               const float* __restrict__ bias,
               float* __restrict__ out)
{
    __shared__ float sc[PB * COEF_PER_PATCH];   // 2400 floats, LINEAR (9600 B)
    __shared__ float sb[128];                   // bias, 120 used (512 B)

    const int tid = threadIdx.x;
    const int b   = blockIdx.x;          // 0..999
    const int pr  = b / 5;               // patch row 0..199
    const int cb  = (b - pr * 5) * PB;   // patch-col base
    const int pbase   = pr * PATCHES_PER_ROW + cb;
    const int colBase = cb * PATCH;      // pixel column base (multiple of 200)

    // ---- Coefficient + bias staging: straight linear cp.async copy ----
    {
        const float4* g4 = (const float4*)(coef + (size_t)pbase * COEF_PER_PATCH);
        #pragma unroll
        for (int k = 0; k < 3; k++) {
            int idx = tid + k * NTHREADS;
            if (idx < 600)
                __pipeline_memcpy_async(&sc[idx * 4], &g4[idx], 16);
        }
        if (tid < 30)
            __pipeline_memcpy_async(&sb[tid * 4],
                                    (const float4*)(bias + (size_t)pbase * 3) + tid, 16);
        __pipeline_commit();
    }

    // ---- Early pixel loads (independent of smem; overlap the coeff wait) ----
    const int p_local = tid % PB;        // 0..39
    const int seg     = tid / PB;        // 0..5 (only 0..4 compute)
    const int pixBase = (pr * PATCH + seg) * IMG_W + colBase + p_local * PATCH;

    unsigned long long xy[PATCH];
    if (tid < PB * PATCH) {
        const double* pp8 = (const double*)pix + pixBase;   // pixel n = double n
        #pragma unroll
        for (int i = 0; i < PATCH; i++)
            xy[i] = as_u64(pp8[i]);
    }

    __pipeline_wait_prior(0);
    __syncthreads();

    // ---- Compute + direct stores (200 threads; thread = 5-pixel segment) ----
    if (tid < PB * PATCH) {
        const float* cc0 = &sc[p_local * COEF_PER_PATCH];   // 240B stride: conflict-free
        const float bv0 = sb[p_local * 3 + 0];
        const float bv1 = sb[p_local * 3 + 1];
        const float bv2 = sb[p_local * 3 + 2];
        float* o = out + pixBase;

        #pragma unroll
        for (int ch = 0; ch < 3; ch++) {
            const double2* cp = (const double2*)(cc0 + ch * 20);  // 16B-aligned
            const float bv = (ch == 0) ? bv0 : (ch == 1) ? bv1 : bv2;

            unsigned long long acc[PATCH];
            {
                double2 v = cp[4];                       // pairs t=8, t=9
                const unsigned long long c8 = as_u64(v.x), c9 = as_u64(v.y);
                #pragma unroll
                for (int i = 0; i < PATCH; i++)
                    acc[i] = ffma2(c9, xy[i], c8);
            }
            #pragma unroll
            for (int j = 3; j >= 0; j--) {
                double2 v = cp[j];                       // pairs t=2j, t=2j+1
                const unsigned long long clo = as_u64(v.x), chi = as_u64(v.y);
                #pragma unroll
                for (int i = 0; i < PATCH; i++)
                    acc[i] = ffma2(acc[i], xy[i], chi);
                #pragma unroll
                for (int i = 0; i < PATCH; i++)
                    acc[i] = ffma2(acc[i], xy[i], clo);
            }
            float* oc = o + ch * NUM_PIX;
            #pragma unroll
            for (int i = 0; i < PATCH; i++)
                oc[i] = hsum2(acc[i]) + bv;              // warp run: contiguous 640B
        }
    }
}

extern "C" void kernel_launch(void* const* d_in, const int* in_sizes, int n_in,
                              void* d_out, int out_size)
{
    const float* pix  = (const float*)d_in[0];   // [1000000, 2]
    const float* coef = (const float*)d_in[1];   // [40000, 3, 10, 2]
    const float* bias = (const float*)d_in[2];   // [40000, 3]
    float* out = (float*)d_out;                  // [3, 1000000]

    (void)in_sizes; (void)n_in; (void)out_size;
    ts_kernel<<<GRID, NTHREADS>>>(pix, coef, bias, out);
}